// round 4
// baseline (speedup 1.0000x reference)
#include <cuda_runtime.h>
#include <cuda_bf16.h>
#include <math.h>

// Problem constants
#define D_MODEL 1024
#define NHEAD   16
#define D_K     64
#define B_SZ    2
#define SEQ     2048
#define M_ROWS  (B_SZ * SEQ)        // 4096

// Scratch (allocation-free rule: __device__ globals)
__device__ float g_Qh[B_SZ * NHEAD * SEQ * D_K];   // [B,H,S,64]
__device__ float g_Kh[B_SZ * NHEAD * SEQ * D_K];
__device__ float g_Vh[B_SZ * NHEAD * SEQ * D_K];
__device__ float g_At[B_SZ * SEQ * D_MODEL];       // [B,S,D] merged heads

// ---------------------------------------------------------------------------
// Tiled SGEMM:  C[M,N] = A[M,K] @ W[N,K]^T + bias[N]
// BM=BN=64, BK=16, 256 threads, 4x4 register tile per thread.
// MODE 0: C row-major [M,N].  MODE 1: head-split write: C=[B,H,S,64].
// ---------------------------------------------------------------------------
template <int MODE>
__global__ void gemm_nt_kernel(const float* __restrict__ A,
                               const float* __restrict__ W,
                               const float* __restrict__ bias,
                               float* __restrict__ C,
                               int M, int N, int K)
{
    __shared__ float As[16][65];
    __shared__ float Bs[16][65];

    const int tid = threadIdx.x;
    const int tx = tid & 15;
    const int ty = tid >> 4;
    const int m0 = blockIdx.y * 64;
    const int n0 = blockIdx.x * 64;

    float acc[4][4];
#pragma unroll
    for (int i = 0; i < 4; i++)
#pragma unroll
        for (int j = 0; j < 4; j++) acc[i][j] = 0.0f;

    for (int k0 = 0; k0 < K; k0 += 16) {
#pragma unroll
        for (int i = 0; i < 4; i++) {
            int lin = tid + i * 256;          // 0..1023
            int mm = lin >> 4;                // 0..63
            int kk = lin & 15;                // 0..15
            As[kk][mm] = A[(m0 + mm) * K + k0 + kk];
            Bs[kk][mm] = W[(n0 + mm) * K + k0 + kk];
        }
        __syncthreads();

#pragma unroll
        for (int kk = 0; kk < 16; kk++) {
            float a[4], b[4];
#pragma unroll
            for (int i = 0; i < 4; i++) a[i] = As[kk][ty + 16 * i];
#pragma unroll
            for (int j = 0; j < 4; j++) b[j] = Bs[kk][tx + 16 * j];
#pragma unroll
            for (int i = 0; i < 4; i++)
#pragma unroll
                for (int j = 0; j < 4; j++)
                    acc[i][j] = fmaf(a[i], b[j], acc[i][j]);
        }
        __syncthreads();
    }

#pragma unroll
    for (int i = 0; i < 4; i++) {
        int m = m0 + ty + 16 * i;
#pragma unroll
        for (int j = 0; j < 4; j++) {
            int n = n0 + tx + 16 * j;
            float v = acc[i][j] + bias[n];
            if (MODE == 0) {
                C[m * N + n] = v;
            } else {
                // m = b*SEQ + s ; n = h*64 + d  -> [B,H,S,64]
                int b  = m >> 11;          // /2048
                int s  = m & 2047;
                int h  = n >> 6;
                int d  = n & 63;
                C[(((b * NHEAD + h) * SEQ) + s) * D_K + d] = v;
            }
        }
    }
}

// ---------------------------------------------------------------------------
// Flash-style attention over head-split Q/K/V.
// Block: 256 threads, one (b,h, 64-row query tile). 64-wide key tiles.
// Online softmax; all-masked prefixes kept at (m=-inf, l=0, P=0) so later
// unmasked keys recover exactly; fully-masked rows end as 0/0 = NaN,
// matching jax softmax(all -inf) semantics.
// ---------------------------------------------------------------------------
__global__ void attn_kernel(const int* __restrict__ qmask,
                            const int* __restrict__ kmask,
                            const int* __restrict__ causal_flag)
{
    extern __shared__ float sm[];
    float* Qs  = sm;               // 64*64
    float* Ks  = Qs + 64 * 64;     // 64*65
    float* Vs  = Ks + 64 * 65;     // 64*64
    float* Ss  = Vs + 64 * 64;     // 64*65
    float* m_s = Ss + 64 * 65;     // 64
    float* l_s = m_s + 64;         // 64
    float* sc_s = l_s + 64;        // 64
    int*   km_s = (int*)(sc_s + 64); // 64

    const int tid = threadIdx.x;
    const int tx = tid & 15;
    const int ty = tid >> 4;
    const int qt = blockIdx.x;         // query tile
    const int bh = blockIdx.y;         // b*NHEAD + h
    const int b  = bh >> 4;
    const int h  = bh & 15;
    const int q0 = qt * 64;
    const int causal = causal_flag[0];

    const int head_base = ((b * NHEAD + h) * SEQ) * D_K;

    // Load Q tile (contiguous 4096 floats)
    {
        const float* src = g_Qh + head_base + q0 * D_K;
#pragma unroll
        for (int i = 0; i < 16; i++) Qs[tid + i * 256] = src[tid + i * 256];
    }
    if (tid < 64) { m_s[tid] = -INFINITY; l_s[tid] = 0.0f; }

    float o[4][4];
#pragma unroll
    for (int i = 0; i < 4; i++)
#pragma unroll
        for (int j = 0; j < 4; j++) o[i][j] = 0.0f;

    const int ntiles = causal ? (qt + 1) : (SEQ / 64);

    __syncthreads();

    for (int kt = 0; kt < ntiles; kt++) {
        const int k0 = kt * 64;
        {
            const float* ksrc = g_Kh + head_base + k0 * D_K;
            const float* vsrc = g_Vh + head_base + k0 * D_K;
#pragma unroll
            for (int i = 0; i < 16; i++) {
                int lin = tid + i * 256;
                int row = lin >> 6;
                int col = lin & 63;
                Ks[row * 65 + col] = ksrc[lin];
                Vs[lin] = vsrc[lin];
            }
        }
        if (tid < 64) km_s[tid] = kmask[b * SEQ + k0 + tid];
        __syncthreads();

        // scores S = Q K^T * (1/8), masked
        float s[4][4];
#pragma unroll
        for (int i = 0; i < 4; i++)
#pragma unroll
            for (int j = 0; j < 4; j++) s[i][j] = 0.0f;

#pragma unroll 8
        for (int d = 0; d < 64; d++) {
            float a[4], bb[4];
#pragma unroll
            for (int i = 0; i < 4; i++) a[i]  = Qs[(ty + 16 * i) * 64 + d];
#pragma unroll
            for (int j = 0; j < 4; j++) bb[j] = Ks[(tx + 16 * j) * 65 + d];
#pragma unroll
            for (int i = 0; i < 4; i++)
#pragma unroll
                for (int j = 0; j < 4; j++)
                    s[i][j] = fmaf(a[i], bb[j], s[i][j]);
        }

#pragma unroll
        for (int i = 0; i < 4; i++) {
            int qg = q0 + ty + 16 * i;
#pragma unroll
            for (int j = 0; j < 4; j++) {
                int kc = tx + 16 * j;
                int kg = k0 + kc;
                bool dead = ((causal != 0) && (kg > qg)) || (km_s[kc] == 0);
                Ss[(ty + 16 * i) * 65 + kc] = dead ? -INFINITY : s[i][j] * 0.125f;
            }
        }
        __syncthreads();

        // online softmax update, one thread per row
        if (tid < 64) {
            const int r = tid;
            float mo = m_s[r];
            float rmax = -INFINITY;
#pragma unroll 8
            for (int j = 0; j < 64; j++) rmax = fmaxf(rmax, Ss[r * 65 + j]);
            float mn = fmaxf(mo, rmax);
            if (mn == -INFINITY) {
                // whole-prefix masked: keep l=0, P=0, no poisoning
#pragma unroll 8
                for (int j = 0; j < 64; j++) Ss[r * 65 + j] = 0.0f;
                sc_s[r] = 1.0f;
            } else {
                float sc = expf(mo - mn);      // mo=-inf -> 0
                float sum = 0.0f;
#pragma unroll 8
                for (int j = 0; j < 64; j++) {
                    float p = expf(Ss[r * 65 + j] - mn);
                    Ss[r * 65 + j] = p;
                    sum += p;
                }
                l_s[r] = l_s[r] * sc + sum;
                m_s[r] = mn;
                sc_s[r] = sc;
            }
        }
        __syncthreads();

        // O = O*scale + P @ V
        float scl[4];
#pragma unroll
        for (int i = 0; i < 4; i++) scl[i] = sc_s[ty + 16 * i];
#pragma unroll
        for (int i = 0; i < 4; i++)
#pragma unroll
            for (int j = 0; j < 4; j++) o[i][j] *= scl[i];

#pragma unroll 8
        for (int kk = 0; kk < 64; kk++) {
            float p[4], v[4];
#pragma unroll
            for (int i = 0; i < 4; i++) p[i] = Ss[(ty + 16 * i) * 65 + kk];
#pragma unroll
            for (int j = 0; j < 4; j++) v[j] = Vs[kk * 64 + tx + 16 * j];
#pragma unroll
            for (int i = 0; i < 4; i++)
#pragma unroll
                for (int j = 0; j < 4; j++)
                    o[i][j] = fmaf(p[i], v[j], o[i][j]);
        }
        __syncthreads();
    }

    // epilogue: divide by l, apply q_mask, write merged-head layout [B,S,D]
#pragma unroll
    for (int i = 0; i < 4; i++) {
        int r  = ty + 16 * i;
        int qg = q0 + r;
        int qm = qmask[b * SEQ + qg];
        float l = l_s[r];
#pragma unroll
        for (int j = 0; j < 4; j++) {
            int d = tx + 16 * j;
            float val = (qm == 0) ? 0.0f : (o[i][j] / l);   // 0/0 -> NaN (matches ref)
            g_At[(b * SEQ + qg) * D_MODEL + h * D_K + d] = val;
        }
    }
}

// ---------------------------------------------------------------------------
extern "C" void kernel_launch(void* const* d_in, const int* in_sizes, int n_in,
                              void* d_out, int out_size)
{
    const float* q  = (const float*)d_in[0];
    const float* k  = (const float*)d_in[1];
    const int*   qm = (const int*)  d_in[2];
    const int*   km = (const int*)  d_in[3];
    const float* Wq = (const float*)d_in[4];
    const float* bq = (const float*)d_in[5];
    const float* Wk = (const float*)d_in[6];
    const float* bk = (const float*)d_in[7];
    const float* Wv = (const float*)d_in[8];
    const float* bv = (const float*)d_in[9];
    const float* Wo = (const float*)d_in[10];
    const float* bo = (const float*)d_in[11];
    const int*   cz = (const int*)  d_in[12];
    float* out = (float*)d_out;

    float *Qh, *Kh, *Vh, *At;
    cudaGetSymbolAddress((void**)&Qh, g_Qh);
    cudaGetSymbolAddress((void**)&Kh, g_Kh);
    cudaGetSymbolAddress((void**)&Vh, g_Vh);
    cudaGetSymbolAddress((void**)&At, g_At);

    dim3 ggrid(D_MODEL / 64, M_ROWS / 64);   // (16, 64)

    // Projections (write head-split)
    gemm_nt_kernel<1><<<ggrid, 256>>>(q, Wq, bq, Qh, M_ROWS, D_MODEL, D_MODEL);
    gemm_nt_kernel<1><<<ggrid, 256>>>(k, Wk, bk, Kh, M_ROWS, D_MODEL, D_MODEL);
    gemm_nt_kernel<1><<<ggrid, 256>>>(k, Wv, bv, Vh, M_ROWS, D_MODEL, D_MODEL);

    // Attention
    size_t smem = (size_t)(64 * 64 + 64 * 65 + 64 * 64 + 64 * 65 + 3 * 64) * sizeof(float)
                + 64 * sizeof(int);
    cudaFuncSetAttribute(attn_kernel, cudaFuncAttributeMaxDynamicSharedMemorySize, (int)smem);
    attn_kernel<<<dim3(SEQ / 64, B_SZ * NHEAD), 256, smem>>>(qm, km, cz);

    // Output projection
    gemm_nt_kernel<0><<<ggrid, 256>>>(At, Wo, bo, out, M_ROWS, D_MODEL, D_MODEL);
}

// round 5
// speedup vs baseline: 3.0200x; 3.0200x over previous
#include <cuda_runtime.h>
#include <cuda_bf16.h>
#include <math.h>
#include <stdint.h>

// Problem constants
#define D_MODEL 1024
#define NHEAD   16
#define D_K     64
#define B_SZ    2
#define SEQ     2048
#define M_ROWS  (B_SZ * SEQ)        // 4096

// Scratch (allocation-free rule: __device__ globals)
__device__ float g_Qh[B_SZ * NHEAD * SEQ * D_K];   // [B,H,S,64]
__device__ float g_Kh[B_SZ * NHEAD * SEQ * D_K];
__device__ float g_Vh[B_SZ * NHEAD * SEQ * D_K];
__device__ float g_At[B_SZ * SEQ * D_MODEL];       // [B,S,D] merged heads

// ---------------------------------------------------------------------------
// TF32 tensor-core GEMM:  C[M,N] = A[M,K] @ W[N,K]^T + bias[N]
// M=4096, N=1024, K=1024 fixed. Block tile 128x128, BK=32.
// 256 threads = 8 warps; warp tile 64x32 = 4x4 fragments of m16n8k8.
// MODE 0: row-major [M,N].  MODE 1: head-split [B,H,S,64].
// ---------------------------------------------------------------------------
__device__ __forceinline__ uint32_t f2tf32(float x) {
    uint32_t r;
    asm("cvt.rna.tf32.f32 %0, %1;" : "=r"(r) : "f"(x));
    return r;
}

#define SM_STRIDE 44   // floats; 44*4B=176B (16B aligned), conflict-free frags

template <int MODE>
__global__ __launch_bounds__(256, 2)
void gemm_tf32_kernel(const float* __restrict__ A,
                      const float* __restrict__ W,
                      const float* __restrict__ bias,
                      float* __restrict__ C)
{
    __shared__ float As[128 * SM_STRIDE];
    __shared__ float Ws[128 * SM_STRIDE];

    const int tid  = threadIdx.x;
    const int warp = tid >> 5;
    const int lane = tid & 31;
    const int g    = lane >> 2;     // group 0..7
    const int tg   = lane & 3;      // thread-in-group 0..3

    const int wm = (warp & 1) * 64;   // warp row offset in block tile
    const int wn = (warp >> 1) * 32;  // warp col offset in block tile

    const int m0 = blockIdx.y * 128;
    const int n0 = blockIdx.x * 128;

    float c[4][4][4];
#pragma unroll
    for (int mi = 0; mi < 4; mi++)
#pragma unroll
        for (int ni = 0; ni < 4; ni++)
#pragma unroll
            for (int r = 0; r < 4; r++) c[mi][ni][r] = 0.0f;

    for (int k0 = 0; k0 < D_MODEL; k0 += 32) {
        // stage 128x32 tiles of A and W (each thread: 4 float4 per tile)
#pragma unroll
        for (int i = 0; i < 4; i++) {
            int idx = tid + i * 256;       // 0..1023 float4 slots
            int r   = idx >> 3;            // 0..127
            int c4  = idx & 7;             // 0..7
            float4 va = *(const float4*)&A[(size_t)(m0 + r) * D_MODEL + k0 + c4 * 4];
            *(float4*)&As[r * SM_STRIDE + c4 * 4] = va;
            float4 vw = *(const float4*)&W[(size_t)(n0 + r) * D_MODEL + k0 + c4 * 4];
            *(float4*)&Ws[r * SM_STRIDE + c4 * 4] = vw;
        }
        __syncthreads();

#pragma unroll
        for (int kk = 0; kk < 32; kk += 8) {
            uint32_t a[4][4], b[4][2];
#pragma unroll
            for (int mi = 0; mi < 4; mi++) {
                int r = wm + mi * 16 + g;
                a[mi][0] = f2tf32(As[r * SM_STRIDE + kk + tg]);
                a[mi][1] = f2tf32(As[(r + 8) * SM_STRIDE + kk + tg]);
                a[mi][2] = f2tf32(As[r * SM_STRIDE + kk + tg + 4]);
                a[mi][3] = f2tf32(As[(r + 8) * SM_STRIDE + kk + tg + 4]);
            }
#pragma unroll
            for (int ni = 0; ni < 4; ni++) {
                int cn = wn + ni * 8 + g;
                b[ni][0] = f2tf32(Ws[cn * SM_STRIDE + kk + tg]);
                b[ni][1] = f2tf32(Ws[cn * SM_STRIDE + kk + tg + 4]);
            }
#pragma unroll
            for (int mi = 0; mi < 4; mi++)
#pragma unroll
                for (int ni = 0; ni < 4; ni++) {
                    asm volatile(
                        "mma.sync.aligned.m16n8k8.row.col.f32.tf32.tf32.f32 "
                        "{%0,%1,%2,%3}, {%4,%5,%6,%7}, {%8,%9}, {%0,%1,%2,%3};"
                        : "+f"(c[mi][ni][0]), "+f"(c[mi][ni][1]),
                          "+f"(c[mi][ni][2]), "+f"(c[mi][ni][3])
                        : "r"(a[mi][0]), "r"(a[mi][1]), "r"(a[mi][2]), "r"(a[mi][3]),
                          "r"(b[ni][0]), "r"(b[ni][1]));
                }
        }
        __syncthreads();
    }

    // Epilogue: add bias, store. Fragment map (m16n8):
    //  c0:(g,     2tg) c1:(g,     2tg+1) c2:(g+8, 2tg) c3:(g+8, 2tg+1)
#pragma unroll
    for (int mi = 0; mi < 4; mi++) {
#pragma unroll
        for (int ni = 0; ni < 4; ni++) {
            int row = m0 + wm + mi * 16 + g;
            int col = n0 + wn + ni * 8 + 2 * tg;
#pragma unroll
            for (int rr = 0; rr < 2; rr++) {       // rr=0 -> rows g, rr=1 -> g+8
                int m = row + rr * 8;
#pragma unroll
                for (int cc = 0; cc < 2; cc++) {
                    int n = col + cc;
                    float v = c[mi][ni][rr * 2 + cc] + bias[n];
                    if (MODE == 0) {
                        C[(size_t)m * D_MODEL + n] = v;
                    } else {
                        int bb = m >> 11;          // /2048
                        int s  = m & 2047;
                        int h  = n >> 6;
                        int d  = n & 63;
                        C[(((size_t)(bb * NHEAD + h) * SEQ) + s) * D_K + d] = v;
                    }
                }
            }
        }
    }
}

// ---------------------------------------------------------------------------
// Flash-style attention over head-split Q/K/V (unchanged this round).
// ---------------------------------------------------------------------------
__global__ void attn_kernel(const int* __restrict__ qmask,
                            const int* __restrict__ kmask,
                            const int* __restrict__ causal_flag)
{
    extern __shared__ float sm[];
    float* Qs  = sm;               // 64*64
    float* Ks  = Qs + 64 * 64;     // 64*65
    float* Vs  = Ks + 64 * 65;     // 64*64
    float* Ss  = Vs + 64 * 64;     // 64*65
    float* m_s = Ss + 64 * 65;     // 64
    float* l_s = m_s + 64;         // 64
    float* sc_s = l_s + 64;        // 64
    int*   km_s = (int*)(sc_s + 64); // 64

    const int tid = threadIdx.x;
    const int tx = tid & 15;
    const int ty = tid >> 4;
    const int qt = blockIdx.x;         // query tile
    const int bh = blockIdx.y;         // b*NHEAD + h
    const int b  = bh >> 4;
    const int h  = bh & 15;
    const int q0 = qt * 64;
    const int causal = causal_flag[0];

    const int head_base = ((b * NHEAD + h) * SEQ) * D_K;

    {
        const float* src = g_Qh + head_base + q0 * D_K;
#pragma unroll
        for (int i = 0; i < 16; i++) Qs[tid + i * 256] = src[tid + i * 256];
    }
    if (tid < 64) { m_s[tid] = -INFINITY; l_s[tid] = 0.0f; }

    float o[4][4];
#pragma unroll
    for (int i = 0; i < 4; i++)
#pragma unroll
        for (int j = 0; j < 4; j++) o[i][j] = 0.0f;

    const int ntiles = causal ? (qt + 1) : (SEQ / 64);

    __syncthreads();

    for (int kt = 0; kt < ntiles; kt++) {
        const int k0 = kt * 64;
        {
            const float* ksrc = g_Kh + head_base + k0 * D_K;
            const float* vsrc = g_Vh + head_base + k0 * D_K;
#pragma unroll
            for (int i = 0; i < 16; i++) {
                int lin = tid + i * 256;
                int row = lin >> 6;
                int col = lin & 63;
                Ks[row * 65 + col] = ksrc[lin];
                Vs[lin] = vsrc[lin];
            }
        }
        if (tid < 64) km_s[tid] = kmask[b * SEQ + k0 + tid];
        __syncthreads();

        float s[4][4];
#pragma unroll
        for (int i = 0; i < 4; i++)
#pragma unroll
            for (int j = 0; j < 4; j++) s[i][j] = 0.0f;

#pragma unroll 8
        for (int d = 0; d < 64; d++) {
            float a[4], bb[4];
#pragma unroll
            for (int i = 0; i < 4; i++) a[i]  = Qs[(ty + 16 * i) * 64 + d];
#pragma unroll
            for (int j = 0; j < 4; j++) bb[j] = Ks[(tx + 16 * j) * 65 + d];
#pragma unroll
            for (int i = 0; i < 4; i++)
#pragma unroll
                for (int j = 0; j < 4; j++)
                    s[i][j] = fmaf(a[i], bb[j], s[i][j]);
        }

#pragma unroll
        for (int i = 0; i < 4; i++) {
            int qg = q0 + ty + 16 * i;
#pragma unroll
            for (int j = 0; j < 4; j++) {
                int kc = tx + 16 * j;
                int kg = k0 + kc;
                bool dead = ((causal != 0) && (kg > qg)) || (km_s[kc] == 0);
                Ss[(ty + 16 * i) * 65 + kc] = dead ? -INFINITY : s[i][j] * 0.125f;
            }
        }
        __syncthreads();

        if (tid < 64) {
            const int r = tid;
            float mo = m_s[r];
            float rmax = -INFINITY;
#pragma unroll 8
            for (int j = 0; j < 64; j++) rmax = fmaxf(rmax, Ss[r * 65 + j]);
            float mn = fmaxf(mo, rmax);
            if (mn == -INFINITY) {
#pragma unroll 8
                for (int j = 0; j < 64; j++) Ss[r * 65 + j] = 0.0f;
                sc_s[r] = 1.0f;
            } else {
                float sc = expf(mo - mn);
                float sum = 0.0f;
#pragma unroll 8
                for (int j = 0; j < 64; j++) {
                    float p = expf(Ss[r * 65 + j] - mn);
                    Ss[r * 65 + j] = p;
                    sum += p;
                }
                l_s[r] = l_s[r] * sc + sum;
                m_s[r] = mn;
                sc_s[r] = sc;
            }
        }
        __syncthreads();

        float scl[4];
#pragma unroll
        for (int i = 0; i < 4; i++) scl[i] = sc_s[ty + 16 * i];
#pragma unroll
        for (int i = 0; i < 4; i++)
#pragma unroll
            for (int j = 0; j < 4; j++) o[i][j] *= scl[i];

#pragma unroll 8
        for (int kk = 0; kk < 64; kk++) {
            float p[4], v[4];
#pragma unroll
            for (int i = 0; i < 4; i++) p[i] = Ss[(ty + 16 * i) * 65 + kk];
#pragma unroll
            for (int j = 0; j < 4; j++) v[j] = Vs[kk * 64 + tx + 16 * j];
#pragma unroll
            for (int i = 0; i < 4; i++)
#pragma unroll
                for (int j = 0; j < 4; j++)
                    o[i][j] = fmaf(p[i], v[j], o[i][j]);
        }
        __syncthreads();
    }

#pragma unroll
    for (int i = 0; i < 4; i++) {
        int r  = ty + 16 * i;
        int qg = q0 + r;
        int qm = qmask[b * SEQ + qg];
        float l = l_s[r];
#pragma unroll
        for (int j = 0; j < 4; j++) {
            int d = tx + 16 * j;
            float val = (qm == 0) ? 0.0f : (o[i][j] / l);   // 0/0 -> NaN (matches ref)
            g_At[(b * SEQ + qg) * D_MODEL + h * D_K + d] = val;
        }
    }
}

// ---------------------------------------------------------------------------
extern "C" void kernel_launch(void* const* d_in, const int* in_sizes, int n_in,
                              void* d_out, int out_size)
{
    const float* q  = (const float*)d_in[0];
    const float* k  = (const float*)d_in[1];
    const int*   qm = (const int*)  d_in[2];
    const int*   km = (const int*)  d_in[3];
    const float* Wq = (const float*)d_in[4];
    const float* bq = (const float*)d_in[5];
    const float* Wk = (const float*)d_in[6];
    const float* bk = (const float*)d_in[7];
    const float* Wv = (const float*)d_in[8];
    const float* bv = (const float*)d_in[9];
    const float* Wo = (const float*)d_in[10];
    const float* bo = (const float*)d_in[11];
    const int*   cz = (const int*)  d_in[12];
    float* out = (float*)d_out;

    float *Qh, *Kh, *Vh, *At;
    cudaGetSymbolAddress((void**)&Qh, g_Qh);
    cudaGetSymbolAddress((void**)&Kh, g_Kh);
    cudaGetSymbolAddress((void**)&Vh, g_Vh);
    cudaGetSymbolAddress((void**)&At, g_At);

    dim3 ggrid(D_MODEL / 128, M_ROWS / 128);   // (8, 32)

    // Projections (tensor-core TF32, write head-split)
    gemm_tf32_kernel<1><<<ggrid, 256>>>(q, Wq, bq, Qh);
    gemm_tf32_kernel<1><<<ggrid, 256>>>(k, Wk, bk, Kh);
    gemm_tf32_kernel<1><<<ggrid, 256>>>(k, Wv, bv, Vh);

    // Attention
    size_t smem = (size_t)(64 * 64 + 64 * 65 + 64 * 64 + 64 * 65 + 3 * 64) * sizeof(float)
                + 64 * sizeof(int);
    cudaFuncSetAttribute(attn_kernel, cudaFuncAttributeMaxDynamicSharedMemorySize, (int)smem);
    attn_kernel<<<dim3(SEQ / 64, B_SZ * NHEAD), 256, smem>>>(qm, km, cz);

    // Output projection (tensor-core TF32)
    gemm_tf32_kernel<0><<<ggrid, 256>>>(At, Wo, bo, out);
}

// round 6
// speedup vs baseline: 5.8702x; 1.9438x over previous
#include <cuda_runtime.h>
#include <cuda_bf16.h>
#include <math.h>
#include <stdint.h>

// Problem constants
#define D_MODEL 1024
#define NHEAD   16
#define D_K     64
#define B_SZ    2
#define SEQ     2048
#define M_ROWS  (B_SZ * SEQ)        // 4096

// Scratch (allocation-free rule: __device__ globals)
__device__ float g_Qh[B_SZ * NHEAD * SEQ * D_K];   // [B,H,S,64]
__device__ float g_Kh[B_SZ * NHEAD * SEQ * D_K];
__device__ float g_Vh[B_SZ * NHEAD * SEQ * D_K];
__device__ float g_At[B_SZ * SEQ * D_MODEL];       // [B,S,D] merged heads

__device__ __forceinline__ uint32_t f2tf32(float x) {
    uint32_t r;
    asm("cvt.rna.tf32.f32 %0, %1;" : "=r"(r) : "f"(x));
    return r;
}

__device__ __forceinline__ void mma_tf32(float c[4], const uint32_t a[4], const uint32_t b[2]) {
    asm volatile(
        "mma.sync.aligned.m16n8k8.row.col.f32.tf32.tf32.f32 "
        "{%0,%1,%2,%3}, {%4,%5,%6,%7}, {%8,%9}, {%0,%1,%2,%3};"
        : "+f"(c[0]), "+f"(c[1]), "+f"(c[2]), "+f"(c[3])
        : "r"(a[0]), "r"(a[1]), "r"(a[2]), "r"(a[3]),
          "r"(b[0]), "r"(b[1]));
}

// ---------------------------------------------------------------------------
// TF32 tensor-core GEMM:  C[M,N] = A[M,K] @ W[N,K]^T + bias[N]
// Block tile 128x128, BK=32, 256 threads = 8 warps (warp tile 64x32).
// MODE 0: row-major [M,N].  MODE 1: head-split [B,H,S,64].
// ---------------------------------------------------------------------------
#define SM_STRIDE 44

template <int MODE>
__global__ __launch_bounds__(256, 2)
void gemm_tf32_kernel(const float* __restrict__ A,
                      const float* __restrict__ W,
                      const float* __restrict__ bias,
                      float* __restrict__ C)
{
    __shared__ float As[128 * SM_STRIDE];
    __shared__ float Ws[128 * SM_STRIDE];

    const int tid  = threadIdx.x;
    const int warp = tid >> 5;
    const int lane = tid & 31;
    const int g    = lane >> 2;
    const int tg   = lane & 3;

    const int wm = (warp & 1) * 64;
    const int wn = (warp >> 1) * 32;

    const int m0 = blockIdx.y * 128;
    const int n0 = blockIdx.x * 128;

    float c[4][4][4];
#pragma unroll
    for (int mi = 0; mi < 4; mi++)
#pragma unroll
        for (int ni = 0; ni < 4; ni++)
#pragma unroll
            for (int r = 0; r < 4; r++) c[mi][ni][r] = 0.0f;

    for (int k0 = 0; k0 < D_MODEL; k0 += 32) {
#pragma unroll
        for (int i = 0; i < 4; i++) {
            int idx = tid + i * 256;
            int r   = idx >> 3;
            int c4  = idx & 7;
            float4 va = *(const float4*)&A[(size_t)(m0 + r) * D_MODEL + k0 + c4 * 4];
            *(float4*)&As[r * SM_STRIDE + c4 * 4] = va;
            float4 vw = *(const float4*)&W[(size_t)(n0 + r) * D_MODEL + k0 + c4 * 4];
            *(float4*)&Ws[r * SM_STRIDE + c4 * 4] = vw;
        }
        __syncthreads();

#pragma unroll
        for (int kk = 0; kk < 32; kk += 8) {
            uint32_t a[4][4], b[4][2];
#pragma unroll
            for (int mi = 0; mi < 4; mi++) {
                int r = wm + mi * 16 + g;
                a[mi][0] = f2tf32(As[r * SM_STRIDE + kk + tg]);
                a[mi][1] = f2tf32(As[(r + 8) * SM_STRIDE + kk + tg]);
                a[mi][2] = f2tf32(As[r * SM_STRIDE + kk + tg + 4]);
                a[mi][3] = f2tf32(As[(r + 8) * SM_STRIDE + kk + tg + 4]);
            }
#pragma unroll
            for (int ni = 0; ni < 4; ni++) {
                int cn = wn + ni * 8 + g;
                b[ni][0] = f2tf32(Ws[cn * SM_STRIDE + kk + tg]);
                b[ni][1] = f2tf32(Ws[cn * SM_STRIDE + kk + tg + 4]);
            }
#pragma unroll
            for (int mi = 0; mi < 4; mi++)
#pragma unroll
                for (int ni = 0; ni < 4; ni++)
                    mma_tf32(c[mi][ni], a[mi], b[ni]);
        }
        __syncthreads();
    }

#pragma unroll
    for (int mi = 0; mi < 4; mi++) {
#pragma unroll
        for (int ni = 0; ni < 4; ni++) {
            int row = m0 + wm + mi * 16 + g;
            int col = n0 + wn + ni * 8 + 2 * tg;
#pragma unroll
            for (int rr = 0; rr < 2; rr++) {
                int m = row + rr * 8;
#pragma unroll
                for (int cc = 0; cc < 2; cc++) {
                    int n = col + cc;
                    float v = c[mi][ni][rr * 2 + cc] + bias[n];
                    if (MODE == 0) {
                        C[(size_t)m * D_MODEL + n] = v;
                    } else {
                        int bb = m >> 11;
                        int s  = m & 2047;
                        int h  = n >> 6;
                        int d  = n & 63;
                        C[(((size_t)(bb * NHEAD + h) * SEQ) + s) * D_K + d] = v;
                    }
                }
            }
        }
    }
}

// ---------------------------------------------------------------------------
// Tensor-core flash attention.
// Block: 128 threads (4 warps), 64 query rows. Key tiles of 64.
// Warp w owns q-rows [w*16, w*16+16). All MMA m16n8k8 tf32.
// Register online softmax: thread owns rows {g, g+8} x 16 cols; quartet
// shfl reductions. P round-trips through warp-private shared slab.
// ---------------------------------------------------------------------------
#define AT_STRIDE 68   // floats; bank = 4g+tg permutation -> conflict-free frags

__global__ __launch_bounds__(128)
void attn_mma_kernel(const int* __restrict__ qmask,
                     const int* __restrict__ kmask,
                     const int* __restrict__ causal_flag)
{
    extern __shared__ float sm[];
    float* Ps  = sm;                         // 64*AT_STRIDE (Q staging, then P)
    float* Ks  = Ps + 64 * AT_STRIDE;        // tf32-converted K tile [key][d]
    float* Vs  = Ks + 64 * AT_STRIDE;        // tf32-converted V tile [key][d]
    int*   km_s = (int*)(Vs + 64 * AT_STRIDE);

    const int tid  = threadIdx.x;
    const int warp = tid >> 5;
    const int lane = tid & 31;
    const int g    = lane >> 2;
    const int tg   = lane & 3;
    const int wrow = warp * 16;

    const int qt = (gridDim.x - 1) - blockIdx.x;   // longest blocks first
    const int bh = blockIdx.y;
    const int b  = bh >> 4;
    const int h  = bh & 15;
    const int q0 = qt * 64;
    const int causal = causal_flag[0];
    const size_t head_base = (size_t)bh * SEQ * D_K;

    // Stage Q tile (plain float) into Ps
    {
        const float* qsrc = g_Qh + head_base + (size_t)q0 * D_K;
#pragma unroll
        for (int i = 0; i < 8; i++) {
            int lin = tid + i * 128;
            int r   = lin >> 4;
            int c4  = (lin & 15) * 4;
            float4 v = *(const float4*)&qsrc[r * 64 + c4];
            *(float4*)&Ps[r * AT_STRIDE + c4] = v;
        }
    }
    __syncthreads();

    // Pre-extract Q A-fragments (tf32) — reused for every key tile
    uint32_t aq[8][4];
#pragma unroll
    for (int kf = 0; kf < 8; kf++) {
        int c = kf * 8;
        aq[kf][0] = f2tf32(Ps[(wrow + g)     * AT_STRIDE + c + tg]);
        aq[kf][1] = f2tf32(Ps[(wrow + g + 8) * AT_STRIDE + c + tg]);
        aq[kf][2] = f2tf32(Ps[(wrow + g)     * AT_STRIDE + c + tg + 4]);
        aq[kf][3] = f2tf32(Ps[(wrow + g + 8) * AT_STRIDE + c + tg + 4]);
    }

    float m_r[2] = { -INFINITY, -INFINITY };
    float l_r[2] = { 0.0f, 0.0f };
    float o[8][4];
#pragma unroll
    for (int nf = 0; nf < 8; nf++)
#pragma unroll
        for (int r = 0; r < 4; r++) o[nf][r] = 0.0f;

    const int ntiles = causal ? (qt + 1) : (SEQ / 64);

    for (int kt = 0; kt < ntiles; kt++) {
        const int k0 = kt * 64;
        __syncthreads();   // previous tile's MMA reads of Ks/Vs done
        {
            const float* ksrc = g_Kh + head_base + (size_t)k0 * D_K;
            const float* vsrc = g_Vh + head_base + (size_t)k0 * D_K;
#pragma unroll
            for (int i = 0; i < 8; i++) {
                int lin = tid + i * 128;
                int r   = lin >> 4;
                int c4  = (lin & 15) * 4;
                float4 kv = *(const float4*)&ksrc[r * 64 + c4];
                kv.x = __uint_as_float(f2tf32(kv.x));
                kv.y = __uint_as_float(f2tf32(kv.y));
                kv.z = __uint_as_float(f2tf32(kv.z));
                kv.w = __uint_as_float(f2tf32(kv.w));
                *(float4*)&Ks[r * AT_STRIDE + c4] = kv;
                float4 vv = *(const float4*)&vsrc[r * 64 + c4];
                vv.x = __uint_as_float(f2tf32(vv.x));
                vv.y = __uint_as_float(f2tf32(vv.y));
                vv.z = __uint_as_float(f2tf32(vv.z));
                vv.w = __uint_as_float(f2tf32(vv.w));
                *(float4*)&Vs[r * AT_STRIDE + c4] = vv;
            }
            if (tid < 64) km_s[tid] = kmask[b * SEQ + k0 + tid];
        }
        __syncthreads();

        // S = Q K^T  (rows wrow..wrow+15, all 64 key cols)
        float cs[8][4];
#pragma unroll
        for (int nf = 0; nf < 8; nf++)
#pragma unroll
            for (int r = 0; r < 4; r++) cs[nf][r] = 0.0f;

#pragma unroll
        for (int kf = 0; kf < 8; kf++) {
            uint32_t bk[8][2];
#pragma unroll
            for (int nf = 0; nf < 8; nf++) {
                bk[nf][0] = __float_as_uint(Ks[(nf * 8 + g) * AT_STRIDE + kf * 8 + tg]);
                bk[nf][1] = __float_as_uint(Ks[(nf * 8 + g) * AT_STRIDE + kf * 8 + tg + 4]);
            }
#pragma unroll
            for (int nf = 0; nf < 8; nf++)
                mma_tf32(cs[nf], aq[kf], bk[nf]);
        }

        // Mask + scale (causal per-element only on diagonal tile)
        const bool diag = (causal != 0) && (kt == qt);
        const int qgA = q0 + wrow + g;
        const int qgB = qgA + 8;
#pragma unroll
        for (int nf = 0; nf < 8; nf++) {
            int colb = nf * 8 + 2 * tg;
            int km0 = km_s[colb];
            int km1 = km_s[colb + 1];
            int kg0 = k0 + colb;
            int kg1 = kg0 + 1;
            float v0 = cs[nf][0] * 0.125f;
            float v1 = cs[nf][1] * 0.125f;
            float v2 = cs[nf][2] * 0.125f;
            float v3 = cs[nf][3] * 0.125f;
            if (km0 == 0 || (diag && kg0 > qgA)) v0 = -INFINITY;
            if (km1 == 0 || (diag && kg1 > qgA)) v1 = -INFINITY;
            if (km0 == 0 || (diag && kg0 > qgB)) v2 = -INFINITY;
            if (km1 == 0 || (diag && kg1 > qgB)) v3 = -INFINITY;
            cs[nf][0] = v0; cs[nf][1] = v1; cs[nf][2] = v2; cs[nf][3] = v3;
        }

        // Register online softmax (two rows per thread)
#pragma unroll
        for (int ri = 0; ri < 2; ri++) {
            float mx = -INFINITY;
#pragma unroll
            for (int nf = 0; nf < 8; nf++) {
                mx = fmaxf(mx, cs[nf][2 * ri]);
                mx = fmaxf(mx, cs[nf][2 * ri + 1]);
            }
            mx = fmaxf(mx, __shfl_xor_sync(0xffffffffu, mx, 1));
            mx = fmaxf(mx, __shfl_xor_sync(0xffffffffu, mx, 2));

            float mo = m_r[ri];
            float mn = fmaxf(mo, mx);
            float sc, sum = 0.0f;
            if (mn == -INFINITY) {
                sc = 1.0f;
#pragma unroll
                for (int nf = 0; nf < 8; nf++) {
                    cs[nf][2 * ri] = 0.0f;
                    cs[nf][2 * ri + 1] = 0.0f;
                }
            } else {
                sc = __expf(mo - mn);          // mo = -inf -> 0
#pragma unroll
                for (int nf = 0; nf < 8; nf++) {
                    float p0 = __expf(cs[nf][2 * ri] - mn);      // -inf -> 0
                    float p1 = __expf(cs[nf][2 * ri + 1] - mn);
                    cs[nf][2 * ri] = p0;
                    cs[nf][2 * ri + 1] = p1;
                    sum += p0 + p1;
                }
                m_r[ri] = mn;
            }
            sum += __shfl_xor_sync(0xffffffffu, sum, 1);
            sum += __shfl_xor_sync(0xffffffffu, sum, 2);
            l_r[ri] = l_r[ri] * sc + sum;

            // rescale O for this row
#pragma unroll
            for (int nf = 0; nf < 8; nf++) {
                o[nf][2 * ri]     *= sc;
                o[nf][2 * ri + 1] *= sc;
            }
            // store P (tf32 bits) into warp-private slab
            int prow = wrow + g + ri * 8;
#pragma unroll
            for (int nf = 0; nf < 8; nf++) {
                Ps[prow * AT_STRIDE + nf * 8 + 2 * tg]     = __uint_as_float(f2tf32(cs[nf][2 * ri]));
                Ps[prow * AT_STRIDE + nf * 8 + 2 * tg + 1] = __uint_as_float(f2tf32(cs[nf][2 * ri + 1]));
            }
        }
        __syncwarp();

        // O += P V   (k dim = 64 keys)
#pragma unroll
        for (int kf = 0; kf < 8; kf++) {
            uint32_t ap[4];
            ap[0] = __float_as_uint(Ps[(wrow + g)     * AT_STRIDE + kf * 8 + tg]);
            ap[1] = __float_as_uint(Ps[(wrow + g + 8) * AT_STRIDE + kf * 8 + tg]);
            ap[2] = __float_as_uint(Ps[(wrow + g)     * AT_STRIDE + kf * 8 + tg + 4]);
            ap[3] = __float_as_uint(Ps[(wrow + g + 8) * AT_STRIDE + kf * 8 + tg + 4]);
#pragma unroll
            for (int nf = 0; nf < 8; nf++) {
                uint32_t bv[2];
                bv[0] = __float_as_uint(Vs[(kf * 8 + tg)     * AT_STRIDE + nf * 8 + g]);
                bv[1] = __float_as_uint(Vs[(kf * 8 + tg + 4) * AT_STRIDE + nf * 8 + g]);
                mma_tf32(o[nf], ap, bv);
            }
        }
        __syncwarp();   // P slab reads done before next-tile overwrite
    }

    // Epilogue: divide by l (0/0 -> NaN matches ref), q_mask, write [B,S,D]
#pragma unroll
    for (int ri = 0; ri < 2; ri++) {
        int r_loc = wrow + g + ri * 8;
        int qg    = q0 + r_loc;
        int qmv   = qmask[b * SEQ + qg];
        float l   = l_r[ri];
        float* dst = g_At + (size_t)(b * SEQ + qg) * D_MODEL + h * D_K;
#pragma unroll
        for (int nf = 0; nf < 8; nf++) {
            float v0 = o[nf][2 * ri]     / l;
            float v1 = o[nf][2 * ri + 1] / l;
            if (qmv == 0) { v0 = 0.0f; v1 = 0.0f; }
            float2 pr = make_float2(v0, v1);
            *(float2*)&dst[nf * 8 + 2 * tg] = pr;
        }
    }
}

// ---------------------------------------------------------------------------
extern "C" void kernel_launch(void* const* d_in, const int* in_sizes, int n_in,
                              void* d_out, int out_size)
{
    const float* q  = (const float*)d_in[0];
    const float* k  = (const float*)d_in[1];
    const int*   qm = (const int*)  d_in[2];
    const int*   km = (const int*)  d_in[3];
    const float* Wq = (const float*)d_in[4];
    const float* bq = (const float*)d_in[5];
    const float* Wk = (const float*)d_in[6];
    const float* bk = (const float*)d_in[7];
    const float* Wv = (const float*)d_in[8];
    const float* bv = (const float*)d_in[9];
    const float* Wo = (const float*)d_in[10];
    const float* bo = (const float*)d_in[11];
    const int*   cz = (const int*)  d_in[12];
    float* out = (float*)d_out;

    float *Qh, *Kh, *Vh, *At;
    cudaGetSymbolAddress((void**)&Qh, g_Qh);
    cudaGetSymbolAddress((void**)&Kh, g_Kh);
    cudaGetSymbolAddress((void**)&Vh, g_Vh);
    cudaGetSymbolAddress((void**)&At, g_At);

    dim3 ggrid(D_MODEL / 128, M_ROWS / 128);   // (8, 32)

    // Projections (tensor-core TF32, write head-split)
    gemm_tf32_kernel<1><<<ggrid, 256>>>(q, Wq, bq, Qh);
    gemm_tf32_kernel<1><<<ggrid, 256>>>(k, Wk, bk, Kh);
    gemm_tf32_kernel<1><<<ggrid, 256>>>(k, Wv, bv, Vh);

    // Tensor-core flash attention
    size_t smem = (size_t)(3 * 64 * AT_STRIDE) * sizeof(float) + 64 * sizeof(int);
    cudaFuncSetAttribute(attn_mma_kernel, cudaFuncAttributeMaxDynamicSharedMemorySize, (int)smem);
    attn_mma_kernel<<<dim3(SEQ / 64, B_SZ * NHEAD), 128, smem>>>(qm, km, cz);

    // Output projection (tensor-core TF32)
    gemm_tf32_kernel<0><<<ggrid, 256>>>(At, Wo, bo, out);
}

// round 10
// speedup vs baseline: 6.2038x; 1.0568x over previous
#include <cuda_runtime.h>
#include <cuda_bf16.h>
#include <math.h>
#include <stdint.h>

// Problem constants
#define D_MODEL 1024
#define NHEAD   16
#define D_K     64
#define B_SZ    2
#define SEQ     2048
#define M_ROWS  (B_SZ * SEQ)        // 4096

// Scratch (allocation-free rule: __device__ globals)
__device__ float g_Qh[B_SZ * NHEAD * SEQ * D_K];   // [B,H,S,64]
__device__ float g_Kh[B_SZ * NHEAD * SEQ * D_K];
__device__ float g_Vh[B_SZ * NHEAD * SEQ * D_K];
__device__ float g_At[B_SZ * SEQ * D_MODEL];       // [B,S,D] merged heads

__device__ __forceinline__ uint32_t f2tf32(float x) {
    uint32_t r;
    asm("cvt.rna.tf32.f32 %0, %1;" : "=r"(r) : "f"(x));
    return r;
}

__device__ __forceinline__ void mma_tf32(float c[4], const uint32_t a[4], const uint32_t b[2]) {
    asm volatile(
        "mma.sync.aligned.m16n8k8.row.col.f32.tf32.tf32.f32 "
        "{%0,%1,%2,%3}, {%4,%5,%6,%7}, {%8,%9}, {%0,%1,%2,%3};"
        : "+f"(c[0]), "+f"(c[1]), "+f"(c[2]), "+f"(c[3])
        : "r"(a[0]), "r"(a[1]), "r"(a[2]), "r"(a[3]),
          "r"(b[0]), "r"(b[1]));
}

// ---------------------------------------------------------------------------
// TF32 tensor-core GEMM body:  C[M,N] = A[M,K] @ W[N,K]^T + bias[N]
// Block tile 128x128, BK=32, 256 threads = 8 warps (warp tile 64x32).
// tf32 conversion hoisted to staging time (inner loop = pure LDS + MMA).
// MODE 0: row-major [M,N].  MODE 1: head-split [B,H,S,64].
// ---------------------------------------------------------------------------
#define SM_STRIDE 44

template <int MODE>
__device__ __forceinline__
void gemm_body(const float* __restrict__ A,
               const float* __restrict__ W,
               const float* __restrict__ bias,
               float* __restrict__ C,
               int m0, int n0)
{
    __shared__ uint32_t As[128 * SM_STRIDE];
    __shared__ uint32_t Ws[128 * SM_STRIDE];

    const int tid  = threadIdx.x;
    const int warp = tid >> 5;
    const int lane = tid & 31;
    const int g    = lane >> 2;
    const int tg   = lane & 3;

    const int wm = (warp & 1) * 64;
    const int wn = (warp >> 1) * 32;

    float c[4][4][4];
#pragma unroll
    for (int mi = 0; mi < 4; mi++)
#pragma unroll
        for (int ni = 0; ni < 4; ni++)
#pragma unroll
            for (int r = 0; r < 4; r++) c[mi][ni][r] = 0.0f;

    for (int k0 = 0; k0 < D_MODEL; k0 += 32) {
        // Stage 128x32 tiles, converting to tf32 bits here (hoisted cvt)
#pragma unroll
        for (int i = 0; i < 4; i++) {
            int idx = tid + i * 256;
            int r   = idx >> 3;
            int c4  = idx & 7;
            float4 va = *(const float4*)&A[(size_t)(m0 + r) * D_MODEL + k0 + c4 * 4];
            uint4 ua = make_uint4(f2tf32(va.x), f2tf32(va.y), f2tf32(va.z), f2tf32(va.w));
            *(uint4*)&As[r * SM_STRIDE + c4 * 4] = ua;
            float4 vw = *(const float4*)&W[(size_t)(n0 + r) * D_MODEL + k0 + c4 * 4];
            uint4 uw = make_uint4(f2tf32(vw.x), f2tf32(vw.y), f2tf32(vw.z), f2tf32(vw.w));
            *(uint4*)&Ws[r * SM_STRIDE + c4 * 4] = uw;
        }
        __syncthreads();

#pragma unroll
        for (int kk = 0; kk < 32; kk += 8) {
            uint32_t a[4][4], b[4][2];
#pragma unroll
            for (int mi = 0; mi < 4; mi++) {
                int r = wm + mi * 16 + g;
                a[mi][0] = As[r * SM_STRIDE + kk + tg];
                a[mi][1] = As[(r + 8) * SM_STRIDE + kk + tg];
                a[mi][2] = As[r * SM_STRIDE + kk + tg + 4];
                a[mi][3] = As[(r + 8) * SM_STRIDE + kk + tg + 4];
            }
#pragma unroll
            for (int ni = 0; ni < 4; ni++) {
                int cn = wn + ni * 8 + g;
                b[ni][0] = Ws[cn * SM_STRIDE + kk + tg];
                b[ni][1] = Ws[cn * SM_STRIDE + kk + tg + 4];
            }
#pragma unroll
            for (int mi = 0; mi < 4; mi++)
#pragma unroll
                for (int ni = 0; ni < 4; ni++)
                    mma_tf32(c[mi][ni], a[mi], b[ni]);
        }
        __syncthreads();
    }

    // Epilogue: add bias, store.
#pragma unroll
    for (int mi = 0; mi < 4; mi++) {
#pragma unroll
        for (int ni = 0; ni < 4; ni++) {
            int row = m0 + wm + mi * 16 + g;
            int col = n0 + wn + ni * 8 + 2 * tg;
#pragma unroll
            for (int rr = 0; rr < 2; rr++) {
                int m = row + rr * 8;
#pragma unroll
                for (int cc = 0; cc < 2; cc++) {
                    int n = col + cc;
                    float v = c[mi][ni][rr * 2 + cc] + bias[n];
                    if (MODE == 0) {
                        C[(size_t)m * D_MODEL + n] = v;
                    } else {
                        int bb = m >> 11;
                        int s  = m & 2047;
                        int h  = n >> 6;
                        int d  = n & 63;
                        C[(((size_t)(bb * NHEAD + h) * SEQ) + s) * D_K + d] = v;
                    }
                }
            }
        }
    }
}

// Batched Q/K/V projection: blockIdx.z selects which GEMM.
__global__ __launch_bounds__(256, 2)
void gemm_proj3_kernel(const float* __restrict__ q,
                       const float* __restrict__ k,
                       const float* __restrict__ Wq, const float* __restrict__ bq,
                       const float* __restrict__ Wk, const float* __restrict__ bk,
                       const float* __restrict__ Wv, const float* __restrict__ bv,
                       float* __restrict__ Qh, float* __restrict__ Kh,
                       float* __restrict__ Vh)
{
    const int z = blockIdx.z;
    const float* A    = (z == 0) ? q  : k;
    const float* W    = (z == 0) ? Wq : (z == 1) ? Wk : Wv;
    const float* bias = (z == 0) ? bq : (z == 1) ? bk : bv;
    float*       C    = (z == 0) ? Qh : (z == 1) ? Kh : Vh;
    gemm_body<1>(A, W, bias, C, blockIdx.y * 128, blockIdx.x * 128);
}

// Output projection (row-major out).
__global__ __launch_bounds__(256, 2)
void gemm_out_kernel(const float* __restrict__ A,
                     const float* __restrict__ W,
                     const float* __restrict__ bias,
                     float* __restrict__ C)
{
    gemm_body<0>(A, W, bias, C, blockIdx.y * 128, blockIdx.x * 128);
}

// ---------------------------------------------------------------------------
// Tensor-core flash attention (proven R6 version).
// Block: 128 threads (4 warps), 64 query rows. Key tiles of 64.
// ---------------------------------------------------------------------------
#define AT_STRIDE 68   // floats; bank = 4g+tg permutation -> conflict-free frags

__global__ __launch_bounds__(128)
void attn_mma_kernel(const int* __restrict__ qmask,
                     const int* __restrict__ kmask,
                     const int* __restrict__ causal_flag)
{
    extern __shared__ float sm[];
    float* Ps  = sm;                         // 64*AT_STRIDE (Q staging, then P)
    float* Ks  = Ps + 64 * AT_STRIDE;        // tf32-converted K tile [key][d]
    float* Vs  = Ks + 64 * AT_STRIDE;        // tf32-converted V tile [key][d]
    int*   km_s = (int*)(Vs + 64 * AT_STRIDE);

    const int tid  = threadIdx.x;
    const int warp = tid >> 5;
    const int lane = tid & 31;
    const int g    = lane >> 2;
    const int tg   = lane & 3;
    const int wrow = warp * 16;

    const int qt = (gridDim.x - 1) - blockIdx.x;   // longest blocks first
    const int bh = blockIdx.y;
    const int b  = bh >> 4;
    const int h  = bh & 15;
    const int q0 = qt * 64;
    const int causal = causal_flag[0];
    const size_t head_base = (size_t)bh * SEQ * D_K;

    {
        const float* qsrc = g_Qh + head_base + (size_t)q0 * D_K;
#pragma unroll
        for (int i = 0; i < 8; i++) {
            int lin = tid + i * 128;
            int r   = lin >> 4;
            int c4  = (lin & 15) * 4;
            float4 v = *(const float4*)&qsrc[r * 64 + c4];
            *(float4*)&Ps[r * AT_STRIDE + c4] = v;
        }
    }
    __syncthreads();

    uint32_t aq[8][4];
#pragma unroll
    for (int kf = 0; kf < 8; kf++) {
        int c = kf * 8;
        aq[kf][0] = f2tf32(Ps[(wrow + g)     * AT_STRIDE + c + tg]);
        aq[kf][1] = f2tf32(Ps[(wrow + g + 8) * AT_STRIDE + c + tg]);
        aq[kf][2] = f2tf32(Ps[(wrow + g)     * AT_STRIDE + c + tg + 4]);
        aq[kf][3] = f2tf32(Ps[(wrow + g + 8) * AT_STRIDE + c + tg + 4]);
    }

    float m_r[2] = { -INFINITY, -INFINITY };
    float l_r[2] = { 0.0f, 0.0f };
    float o[8][4];
#pragma unroll
    for (int nf = 0; nf < 8; nf++)
#pragma unroll
        for (int r = 0; r < 4; r++) o[nf][r] = 0.0f;

    const int ntiles = causal ? (qt + 1) : (SEQ / 64);

    for (int kt = 0; kt < ntiles; kt++) {
        const int k0 = kt * 64;
        __syncthreads();   // previous tile's MMA reads of Ks/Vs done
        {
            const float* ksrc = g_Kh + head_base + (size_t)k0 * D_K;
            const float* vsrc = g_Vh + head_base + (size_t)k0 * D_K;
#pragma unroll
            for (int i = 0; i < 8; i++) {
                int lin = tid + i * 128;
                int r   = lin >> 4;
                int c4  = (lin & 15) * 4;
                float4 kv = *(const float4*)&ksrc[r * 64 + c4];
                kv.x = __uint_as_float(f2tf32(kv.x));
                kv.y = __uint_as_float(f2tf32(kv.y));
                kv.z = __uint_as_float(f2tf32(kv.z));
                kv.w = __uint_as_float(f2tf32(kv.w));
                *(float4*)&Ks[r * AT_STRIDE + c4] = kv;
                float4 vv = *(const float4*)&vsrc[r * 64 + c4];
                vv.x = __uint_as_float(f2tf32(vv.x));
                vv.y = __uint_as_float(f2tf32(vv.y));
                vv.z = __uint_as_float(f2tf32(vv.z));
                vv.w = __uint_as_float(f2tf32(vv.w));
                *(float4*)&Vs[r * AT_STRIDE + c4] = vv;
            }
            if (tid < 64) km_s[tid] = kmask[b * SEQ + k0 + tid];
        }
        __syncthreads();

        float cs[8][4];
#pragma unroll
        for (int nf = 0; nf < 8; nf++)
#pragma unroll
            for (int r = 0; r < 4; r++) cs[nf][r] = 0.0f;

#pragma unroll
        for (int kf = 0; kf < 8; kf++) {
            uint32_t bk[8][2];
#pragma unroll
            for (int nf = 0; nf < 8; nf++) {
                bk[nf][0] = __float_as_uint(Ks[(nf * 8 + g) * AT_STRIDE + kf * 8 + tg]);
                bk[nf][1] = __float_as_uint(Ks[(nf * 8 + g) * AT_STRIDE + kf * 8 + tg + 4]);
            }
#pragma unroll
            for (int nf = 0; nf < 8; nf++)
                mma_tf32(cs[nf], aq[kf], bk[nf]);
        }

        const bool diag = (causal != 0) && (kt == qt);
        const int qgA = q0 + wrow + g;
        const int qgB = qgA + 8;
#pragma unroll
        for (int nf = 0; nf < 8; nf++) {
            int colb = nf * 8 + 2 * tg;
            int km0 = km_s[colb];
            int km1 = km_s[colb + 1];
            int kg0 = k0 + colb;
            int kg1 = kg0 + 1;
            float v0 = cs[nf][0] * 0.125f;
            float v1 = cs[nf][1] * 0.125f;
            float v2 = cs[nf][2] * 0.125f;
            float v3 = cs[nf][3] * 0.125f;
            if (km0 == 0 || (diag && kg0 > qgA)) v0 = -INFINITY;
            if (km1 == 0 || (diag && kg1 > qgA)) v1 = -INFINITY;
            if (km0 == 0 || (diag && kg0 > qgB)) v2 = -INFINITY;
            if (km1 == 0 || (diag && kg1 > qgB)) v3 = -INFINITY;
            cs[nf][0] = v0; cs[nf][1] = v1; cs[nf][2] = v2; cs[nf][3] = v3;
        }

#pragma unroll
        for (int ri = 0; ri < 2; ri++) {
            float mx = -INFINITY;
#pragma unroll
            for (int nf = 0; nf < 8; nf++) {
                mx = fmaxf(mx, cs[nf][2 * ri]);
                mx = fmaxf(mx, cs[nf][2 * ri + 1]);
            }
            mx = fmaxf(mx, __shfl_xor_sync(0xffffffffu, mx, 1));
            mx = fmaxf(mx, __shfl_xor_sync(0xffffffffu, mx, 2));

            float mo = m_r[ri];
            float mn = fmaxf(mo, mx);
            float sc, sum = 0.0f;
            if (mn == -INFINITY) {
                sc = 1.0f;
#pragma unroll
                for (int nf = 0; nf < 8; nf++) {
                    cs[nf][2 * ri] = 0.0f;
                    cs[nf][2 * ri + 1] = 0.0f;
                }
            } else {
                sc = __expf(mo - mn);          // mo = -inf -> 0
#pragma unroll
                for (int nf = 0; nf < 8; nf++) {
                    float p0 = __expf(cs[nf][2 * ri] - mn);      // -inf -> 0
                    float p1 = __expf(cs[nf][2 * ri + 1] - mn);
                    cs[nf][2 * ri] = p0;
                    cs[nf][2 * ri + 1] = p1;
                    sum += p0 + p1;
                }
                m_r[ri] = mn;
            }
            sum += __shfl_xor_sync(0xffffffffu, sum, 1);
            sum += __shfl_xor_sync(0xffffffffu, sum, 2);
            l_r[ri] = l_r[ri] * sc + sum;

#pragma unroll
            for (int nf = 0; nf < 8; nf++) {
                o[nf][2 * ri]     *= sc;
                o[nf][2 * ri + 1] *= sc;
            }
            int prow = wrow + g + ri * 8;
#pragma unroll
            for (int nf = 0; nf < 8; nf++) {
                Ps[prow * AT_STRIDE + nf * 8 + 2 * tg]     = __uint_as_float(f2tf32(cs[nf][2 * ri]));
                Ps[prow * AT_STRIDE + nf * 8 + 2 * tg + 1] = __uint_as_float(f2tf32(cs[nf][2 * ri + 1]));
            }
        }
        __syncwarp();

#pragma unroll
        for (int kf = 0; kf < 8; kf++) {
            uint32_t ap[4];
            ap[0] = __float_as_uint(Ps[(wrow + g)     * AT_STRIDE + kf * 8 + tg]);
            ap[1] = __float_as_uint(Ps[(wrow + g + 8) * AT_STRIDE + kf * 8 + tg]);
            ap[2] = __float_as_uint(Ps[(wrow + g)     * AT_STRIDE + kf * 8 + tg + 4]);
            ap[3] = __float_as_uint(Ps[(wrow + g + 8) * AT_STRIDE + kf * 8 + tg + 4]);
#pragma unroll
            for (int nf = 0; nf < 8; nf++) {
                uint32_t bv[2];
                bv[0] = __float_as_uint(Vs[(kf * 8 + tg)     * AT_STRIDE + nf * 8 + g]);
                bv[1] = __float_as_uint(Vs[(kf * 8 + tg + 4) * AT_STRIDE + nf * 8 + g]);
                mma_tf32(o[nf], ap, bv);
            }
        }
        __syncwarp();   // P slab reads done before next-tile overwrite
    }

#pragma unroll
    for (int ri = 0; ri < 2; ri++) {
        int r_loc = wrow + g + ri * 8;
        int qg    = q0 + r_loc;
        int qmv   = qmask[b * SEQ + qg];
        float l   = l_r[ri];
        float* dst = g_At + (size_t)(b * SEQ + qg) * D_MODEL + h * D_K;
#pragma unroll
        for (int nf = 0; nf < 8; nf++) {
            float v0 = o[nf][2 * ri]     / l;
            float v1 = o[nf][2 * ri + 1] / l;
            if (qmv == 0) { v0 = 0.0f; v1 = 0.0f; }
            float2 pr = make_float2(v0, v1);
            *(float2*)&dst[nf * 8 + 2 * tg] = pr;
        }
    }
}

// ---------------------------------------------------------------------------
extern "C" void kernel_launch(void* const* d_in, const int* in_sizes, int n_in,
                              void* d_out, int out_size)
{
    const float* q  = (const float*)d_in[0];
    const float* k  = (const float*)d_in[1];
    const int*   qm = (const int*)  d_in[2];
    const int*   km = (const int*)  d_in[3];
    const float* Wq = (const float*)d_in[4];
    const float* bq = (const float*)d_in[5];
    const float* Wk = (const float*)d_in[6];
    const float* bk = (const float*)d_in[7];
    const float* Wv = (const float*)d_in[8];
    const float* bv = (const float*)d_in[9];
    const float* Wo = (const float*)d_in[10];
    const float* bo = (const float*)d_in[11];
    const int*   cz = (const int*)  d_in[12];
    float* out = (float*)d_out;

    float *Qh, *Kh, *Vh, *At;
    cudaGetSymbolAddress((void**)&Qh, g_Qh);
    cudaGetSymbolAddress((void**)&Kh, g_Kh);
    cudaGetSymbolAddress((void**)&Vh, g_Vh);
    cudaGetSymbolAddress((void**)&At, g_At);

    // Batched Q/K/V projections (one launch, z = which GEMM)
    dim3 pgrid(D_MODEL / 128, M_ROWS / 128, 3);   // (8, 32, 3)
    gemm_proj3_kernel<<<pgrid, 256>>>(q, k, Wq, bq, Wk, bk, Wv, bv, Qh, Kh, Vh);

    // Tensor-core flash attention
    size_t smem = (size_t)(3 * 64 * AT_STRIDE) * sizeof(float) + 64 * sizeof(int);
    cudaFuncSetAttribute(attn_mma_kernel, cudaFuncAttributeMaxDynamicSharedMemorySize, (int)smem);
    attn_mma_kernel<<<dim3(SEQ / 64, B_SZ * NHEAD), 128, smem>>>(qm, km, cz);

    // Output projection
    dim3 ogrid(D_MODEL / 128, M_ROWS / 128);      // (8, 32)
    gemm_out_kernel<<<ogrid, 256>>>(At, Wo, bo, out);
}